// round 13
// baseline (speedup 1.0000x reference)
#include <cuda_runtime.h>
#include <cstdint>

// Problem constants
#define B_DIM 128
#define G_DIM 20000
#define N_ELEM (B_DIM * G_DIM)   // 2,560,000
#define HID 64
#define NBM1 9                   // NUM_BINS - 1
#define NBINS 10
#define NSEG (HID + 1)           // 65 piecewise-linear segments
#define ROWF 20                  // floats per table row (A0..A8,C0..C8,pad,pad) = 80B
#define BLK 256
#define EPT 2                    // elements per thread
#define EPB (BLK * EPT)          // 512 elements per block
#define NBLK (N_ELEM / EPB)      // 5,000
#define LOG2E 1.4426950408889634f

// __device__ global scratch (no allocations allowed)
__device__ float g_T[HID];                          // sorted thresholds
__device__ __align__(16) float g_tab[NSEG * ROWF];  // log2-domain (A', C') table

// ---------------------------------------------------------------------------
// Setup: build the piecewise-linear table (log2 domain), parallelized:
// grid = NSEG blocks (one segment each), 288 threads (9 warps; warp k
// reduces entry (j,k) over h with shuffles).
// logit_k(x) = b2[k] + sum_h W2[h,k] * leaky(x*w1[h] + b1[h]); the leaky
// sign pattern changes only at thr_h = -b1[h]/w1[h]. For segment j:
//   w1>0 : pre-act >= 0  <=>  rank(thr_h) < j
//   w1<0 : pre-act >= 0  <=>  rank(thr_h) >= j
//   w1==0: pre-act >= 0  <=>  b1 >= 0     (thr = +inf, excluded from search)
// ---------------------------------------------------------------------------
__global__ void setup_kernel(const float* __restrict__ W1,
                             const float* __restrict__ b1,
                             const float* __restrict__ W2,
                             const float* __restrict__ b2) {
    __shared__ float s_thr[HID];
    __shared__ int   s_rank[HID];
    __shared__ float s_w1[HID];
    __shared__ float s_b1[HID];

    int t = threadIdx.x;
    if (t < HID) {
        float w = W1[t];
        float b = b1[t];
        s_w1[t] = w;
        s_b1[t] = b;
        s_thr[t] = (w != 0.0f) ? (-b / w) : __int_as_float(0x7f800000); // +inf
    }
    __syncthreads();

    if (t < HID) {
        float thr = s_thr[t];
        int idx = 0;
        #pragma unroll
        for (int h = 0; h < HID; h++) {
            float o = s_thr[h];
            if (o < thr || (o == thr && h < t)) idx++;  // stable rank
        }
        s_rank[t] = idx;
        if (blockIdx.x == 0) g_T[idx] = thr;  // only one block writes g_T
    }
    __syncthreads();

    int j    = blockIdx.x;       // segment
    int k    = t >> 5;           // warp id = bin
    int lane = t & 31;
    if (k < NBM1) {
        float A = 0.0f, C = 0.0f;
        #pragma unroll
        for (int hh = 0; hh < 2; hh++) {
            int h = lane + 32 * hh;
            float w = s_w1[h];
            float b = s_b1[h];
            bool pos;
            if (w > 0.0f)      pos = (s_rank[h] < j);
            else if (w < 0.0f) pos = (s_rank[h] >= j);
            else               pos = (b >= 0.0f);
            float scale = pos ? 1.0f : 0.01f;
            float w2s = W2[h * NBM1 + k] * scale;
            A = fmaf(w2s, w, A);
            C = fmaf(w2s, b, C);
        }
        #pragma unroll
        for (int off = 16; off > 0; off >>= 1) {
            A += __shfl_down_sync(0xffffffffu, A, off);
            C += __shfl_down_sync(0xffffffffu, C, off);
        }
        if (lane == 0) {
            g_tab[j * ROWF + k]        = A * LOG2E;
            g_tab[j * ROWF + NBM1 + k] = (C + b2[k]) * LOG2E;
        }
    }
    if (t == 288 - 1) {  // zero row padding
        g_tab[j * ROWF + 18] = 0.0f;
        g_tab[j * ROWF + 19] = 0.0f;
    }
}

// ---------------------------------------------------------------------------
// Main: 2 elements/thread, sparsity-compacted compute, TMA bulk-store flush.
// Per block: 512 elements, 20 KB staging. Zero path is float2/float4 traffic
// only; ~51 nonzero elements are compacted via one shared-counter atomicAdd
// per thread and processed by the first couple of warps, reading table rows
// straight from global (L1-hot). One cp.async.bulk flushes the staging
// buffer through the async proxy (no LSU/L1 involvement).
// ---------------------------------------------------------------------------
__global__ void __launch_bounds__(BLK)
expr_quantizer_kernel(const float* __restrict__ expr,
                      float* __restrict__ probs,
                      float* __restrict__ mask) {
    __shared__ __align__(16) float sOut[EPB * NBINS];  // 20 KB staging
    __shared__ float s_xv[EPB];
    __shared__ int   s_xi[EPB];
    __shared__ int   s_cnt;

    int t = threadIdx.x;

    // Issue the expr load early (latency cover for the prefill)
    int e0 = blockIdx.x * EPB + 2 * t;               // even -> 8B aligned
    float2 xv = __ldg(reinterpret_cast<const float2*>(expr + e0));

    if (t == 0) s_cnt = 0;

    // Zero-prefill staging: 1280 float4s, 5 per thread
    {
        float4 z = make_float4(0.0f, 0.0f, 0.0f, 0.0f);
        float4* so4 = reinterpret_cast<float4*>(sOut);
        #pragma unroll
        for (int i = 0; i < 5; i++) so4[t + BLK * i] = z;
    }
    __syncthreads();

    bool nz0 = (xv.x != 0.0f);
    bool nz1 = (xv.y != 0.0f);

    // mask: coalesced float2 store
    *reinterpret_cast<float2*>(mask + e0) =
        make_float2(nz0 ? 1.0f : 0.0f, nz1 ? 1.0f : 0.0f);

    // bin-0 probability for both rows
    sOut[(2 * t) * NBINS]     = nz0 ? 0.0f : 1.0f;
    sOut[(2 * t + 1) * NBINS] = nz1 ? 0.0f : 1.0f;

    // compact both nonzeros with a single atomic
    int c = (int)nz0 + (int)nz1;
    if (c) {
        int p = atomicAdd(&s_cnt, c);
        if (nz0) { s_xv[p] = xv.x; s_xi[p] = 2 * t;     p++; }
        if (nz1) { s_xv[p] = xv.y; s_xi[p] = 2 * t + 1; }
    }
    __syncthreads();

    int n = s_cnt;
    for (int i = t; i < n; i += BLK) {
        float xx = s_xv[i];
        int idx = s_xi[i];

        // j = count of sorted thresholds <= xx, in [0, 64] (L1-hot LDGs)
        int j = 0;
        #pragma unroll
        for (int step = 64; step > 0; step >>= 1) {
            int nj = j + step;
            if (nj <= HID && __ldg(g_T + nj - 1) <= xx) j = nj;
        }

        const float4* row = reinterpret_cast<const float4*>(g_tab + j * ROWF);
        float4 r0 = __ldg(row + 0);  // A0..A3
        float4 r1 = __ldg(row + 1);  // A4..A7
        float4 r2 = __ldg(row + 2);  // A8, C0, C1, C2
        float4 r3 = __ldg(row + 3);  // C3..C6
        float4 r4 = __ldg(row + 4);  // C7, C8, pad, pad

        float l0 = fmaf(r0.x, xx, r2.y);
        float l1 = fmaf(r0.y, xx, r2.z);
        float l2 = fmaf(r0.z, xx, r2.w);
        float l3 = fmaf(r0.w, xx, r3.x);
        float l4 = fmaf(r1.x, xx, r3.y);
        float l5 = fmaf(r1.y, xx, r3.z);
        float l6 = fmaf(r1.z, xx, r3.w);
        float l7 = fmaf(r1.w, xx, r4.x);
        float l8 = fmaf(r2.x, xx, r4.y);

        float m0 = fmaxf(l0, l1), m1 = fmaxf(l2, l3);
        float m2 = fmaxf(l4, l5), m3 = fmaxf(l6, l7);
        float mx = fmaxf(fmaxf(fmaxf(m0, m1), fmaxf(m2, m3)), l8);

        float e0v = exp2f(l0 - mx), e1v = exp2f(l1 - mx), e2v = exp2f(l2 - mx);
        float e3v = exp2f(l3 - mx), e4v = exp2f(l4 - mx), e5v = exp2f(l5 - mx);
        float e6v = exp2f(l6 - mx), e7v = exp2f(l7 - mx), e8v = exp2f(l8 - mx);

        float s0 = e0v + e1v, s1 = e2v + e3v, s2 = e4v + e5v, s3 = e6v + e7v;
        float sum = ((s0 + s1) + (s2 + s3)) + e8v;
        float inv = __fdividef(1.0f, sum);

        float* o = &sOut[idx * NBINS];
        o[1] = e0v * inv; o[2] = e1v * inv; o[3] = e2v * inv;
        o[4] = e3v * inv; o[5] = e4v * inv; o[6] = e5v * inv;
        o[7] = e6v * inv; o[8] = e7v * inv; o[9] = e8v * inv;
    }
    __syncthreads();

    // TMA bulk-store flush: 20480B contiguous, 16B-aligned both sides.
    if (t == 0) {
        asm volatile("fence.proxy.async.shared::cta;" ::: "memory");
        uint32_t ssrc = (uint32_t)__cvta_generic_to_shared(sOut);
        void* gdst = (void*)(probs + (size_t)blockIdx.x * (EPB * NBINS));
        asm volatile(
            "cp.async.bulk.global.shared::cta.bulk_group [%0], [%1], %2;"
            :: "l"(gdst), "r"(ssrc), "n"(EPB * NBINS * 4) : "memory");
        asm volatile("cp.async.bulk.commit_group;" ::: "memory");
        // smem must stay alive until the bulk read completes
        asm volatile("cp.async.bulk.wait_group.read 0;" ::: "memory");
    }
}

extern "C" void kernel_launch(void* const* d_in, const int* in_sizes, int n_in,
                              void* d_out, int out_size) {
    const float* expr = (const float*)d_in[0];
    const float* W1   = (const float*)d_in[1];
    const float* b1   = (const float*)d_in[2];
    const float* W2   = (const float*)d_in[3];
    const float* b2   = (const float*)d_in[4];

    float* probs = (float*)d_out;
    float* mask  = (float*)d_out + (size_t)N_ELEM * NBINS;

    setup_kernel<<<NSEG, 288>>>(W1, b1, W2, b2);
    expr_quantizer_kernel<<<NBLK, BLK>>>(expr, probs, mask);
}

// round 14
// speedup vs baseline: 1.2074x; 1.2074x over previous
#include <cuda_runtime.h>
#include <cstdint>

// Problem constants
#define B_DIM 128
#define G_DIM 20000
#define N_ELEM (B_DIM * G_DIM)   // 2,560,000
#define HID 64
#define NBM1 9                   // NUM_BINS - 1
#define NBINS 10
#define NSEG (HID + 1)           // 65 piecewise-linear segments
#define ROWF 20                  // floats per table row (A0..A8,C0..C8,pad,pad) = 80B
#define BLK 256
#define NTILE (N_ELEM / BLK)     // 10,000 tiles of 256 elements
#define PGRID 1184               // persistent CTAs: 148 SMs x 8
#define LOG2E 1.4426950408889634f

// __device__ global scratch (no allocations allowed)
__device__ float g_T[HID];                          // sorted thresholds
__device__ __align__(16) float g_tab[NSEG * ROWF];  // log2-domain (A', C') table

// ---------------------------------------------------------------------------
// Setup: build the piecewise-linear table (log2 domain), parallelized:
// grid = NSEG blocks (one segment each), 288 threads (9 warps; warp k
// reduces entry (j,k) over h with shuffles).
// logit_k(x) = b2[k] + sum_h W2[h,k] * leaky(x*w1[h] + b1[h]); the leaky
// sign pattern changes only at thr_h = -b1[h]/w1[h]. For segment j:
//   w1>0 : pre-act >= 0  <=>  rank(thr_h) < j
//   w1<0 : pre-act >= 0  <=>  rank(thr_h) >= j
//   w1==0: pre-act >= 0  <=>  b1 >= 0     (thr = +inf, excluded from search)
// ---------------------------------------------------------------------------
__global__ void setup_kernel(const float* __restrict__ W1,
                             const float* __restrict__ b1,
                             const float* __restrict__ W2,
                             const float* __restrict__ b2) {
    __shared__ float s_thr[HID];
    __shared__ int   s_rank[HID];
    __shared__ float s_w1[HID];
    __shared__ float s_b1[HID];

    int t = threadIdx.x;
    if (t < HID) {
        float w = W1[t];
        float b = b1[t];
        s_w1[t] = w;
        s_b1[t] = b;
        s_thr[t] = (w != 0.0f) ? (-b / w) : __int_as_float(0x7f800000); // +inf
    }
    __syncthreads();

    if (t < HID) {
        float thr = s_thr[t];
        int idx = 0;
        #pragma unroll
        for (int h = 0; h < HID; h++) {
            float o = s_thr[h];
            if (o < thr || (o == thr && h < t)) idx++;  // stable rank
        }
        s_rank[t] = idx;
        if (blockIdx.x == 0) g_T[idx] = thr;  // only one block writes g_T
    }
    __syncthreads();

    int j    = blockIdx.x;       // segment
    int k    = t >> 5;           // warp id = bin
    int lane = t & 31;
    if (k < NBM1) {
        float A = 0.0f, C = 0.0f;
        #pragma unroll
        for (int hh = 0; hh < 2; hh++) {
            int h = lane + 32 * hh;
            float w = s_w1[h];
            float b = s_b1[h];
            bool pos;
            if (w > 0.0f)      pos = (s_rank[h] < j);
            else if (w < 0.0f) pos = (s_rank[h] >= j);
            else               pos = (b >= 0.0f);
            float scale = pos ? 1.0f : 0.01f;
            float w2s = W2[h * NBM1 + k] * scale;
            A = fmaf(w2s, w, A);
            C = fmaf(w2s, b, C);
        }
        #pragma unroll
        for (int off = 16; off > 0; off >>= 1) {
            A += __shfl_down_sync(0xffffffffu, A, off);
            C += __shfl_down_sync(0xffffffffu, C, off);
        }
        if (lane == 0) {
            g_tab[j * ROWF + k]        = A * LOG2E;
            g_tab[j * ROWF + NBM1 + k] = (C + b2[k]) * LOG2E;
        }
    }
    if (t == 288 - 1) {  // zero row padding
        g_tab[j * ROWF + 18] = 0.0f;
        g_tab[j * ROWF + 19] = 0.0f;
    }
}

// ---------------------------------------------------------------------------
// Main: PERSISTENT CTAs, double-buffered staging + TMA bulk-store.
// Each of 1184 CTAs loops over ~8.5 tiles of 256 elements. Per tile:
//   phase A: each thread writes its own 40B output row as 5 STS.64
//            (bin0 folded in; no cross-thread prefill conflict -> no extra
//            barrier), stores mask, compacts nonzeros via shared atomic.
//   phase B: first n threads run search+softmax, scatter 9 probs.
//   flush:   one cp.async.bulk (shared->global) per tile; buffers alternate,
//            wait_group.read 1 pipelines the TMA drain behind the next
//            tile's compute. Tail-wait happens ONCE per CTA, not per tile.
// ---------------------------------------------------------------------------
__global__ void __launch_bounds__(BLK)
expr_quantizer_kernel(const float* __restrict__ expr,
                      float* __restrict__ probs,
                      float* __restrict__ mask) {
    __shared__ __align__(16) float sOut[2][BLK * NBINS];  // 2 x 10 KB staging
    __shared__ float sT[HID];
    __shared__ float s_xv[BLK];
    __shared__ int   s_xi[BLK];
    __shared__ int   s_cnt[2];

    int t = threadIdx.x;
    if (t < HID) sT[t] = g_T[t];
    if (t < 2) s_cnt[t] = 0;
    __syncthreads();

    int j = 0;  // local iteration index
    for (int tile = blockIdx.x; tile < NTILE; tile += PGRID, j++) {
        int b = j & 1;
        float* out = sOut[b];

        // ---- phase A ----
        int e = tile * BLK + t;
        float x = __ldg(expr + e);
        bool nz = (x != 0.0f);

        // own-row init: 5 x STS.64, row base = t*40B (8B-aligned for all t)
        {
            float2* row2 = reinterpret_cast<float2*>(out + t * NBINS);
            row2[0] = make_float2(nz ? 0.0f : 1.0f, 0.0f);
            float2 z2 = make_float2(0.0f, 0.0f);
            row2[1] = z2; row2[2] = z2; row2[3] = z2; row2[4] = z2;
        }
        mask[e] = nz ? 1.0f : 0.0f;
        if (t == 0) s_cnt[b ^ 1] = 0;       // reset other buffer's counter
        if (nz) {
            int p = atomicAdd(&s_cnt[b], 1);
            s_xv[p] = x;
            s_xi[p] = t;
        }
        __syncthreads();

        // ---- phase B ----
        int n = s_cnt[b];
        if (t < n) {
            float xx = s_xv[t];
            int idx = s_xi[t];

            // segment = count of sorted thresholds <= xx, in [0, 64]
            int sj = 0;
            #pragma unroll
            for (int step = 64; step > 0; step >>= 1) {
                int nj = sj + step;
                if (nj <= HID && sT[nj - 1] <= xx) sj = nj;
            }

            const float4* row = reinterpret_cast<const float4*>(g_tab + sj * ROWF);
            float4 r0 = __ldg(row + 0);  // A0..A3
            float4 r1 = __ldg(row + 1);  // A4..A7
            float4 r2 = __ldg(row + 2);  // A8, C0, C1, C2
            float4 r3 = __ldg(row + 3);  // C3..C6
            float4 r4 = __ldg(row + 4);  // C7, C8, pad, pad

            float l0 = fmaf(r0.x, xx, r2.y);
            float l1 = fmaf(r0.y, xx, r2.z);
            float l2 = fmaf(r0.z, xx, r2.w);
            float l3 = fmaf(r0.w, xx, r3.x);
            float l4 = fmaf(r1.x, xx, r3.y);
            float l5 = fmaf(r1.y, xx, r3.z);
            float l6 = fmaf(r1.z, xx, r3.w);
            float l7 = fmaf(r1.w, xx, r4.x);
            float l8 = fmaf(r2.x, xx, r4.y);

            float m0 = fmaxf(l0, l1), m1 = fmaxf(l2, l3);
            float m2 = fmaxf(l4, l5), m3 = fmaxf(l6, l7);
            float mx = fmaxf(fmaxf(fmaxf(m0, m1), fmaxf(m2, m3)), l8);

            float e0 = exp2f(l0 - mx), e1 = exp2f(l1 - mx), e2 = exp2f(l2 - mx);
            float e3 = exp2f(l3 - mx), e4 = exp2f(l4 - mx), e5 = exp2f(l5 - mx);
            float e6 = exp2f(l6 - mx), e7 = exp2f(l7 - mx), e8 = exp2f(l8 - mx);

            float s0 = e0 + e1, s1 = e2 + e3, s2 = e4 + e5, s3 = e6 + e7;
            float sum = ((s0 + s1) + (s2 + s3)) + e8;
            float inv = __fdividef(1.0f, sum);

            float* o = out + idx * NBINS;
            o[1] = e0 * inv; o[2] = e1 * inv; o[3] = e2 * inv;
            o[4] = e3 * inv; o[5] = e4 * inv; o[6] = e5 * inv;
            o[7] = e6 * inv; o[8] = e7 * inv; o[9] = e8 * inv;
        }
        __syncthreads();

        // ---- flush (pipelined) ----
        if (t == 0) {
            asm volatile("fence.proxy.async.shared::cta;" ::: "memory");
            uint32_t ssrc = (uint32_t)__cvta_generic_to_shared(out);
            void* gdst = (void*)(probs + (size_t)tile * (BLK * NBINS));
            asm volatile(
                "cp.async.bulk.global.shared::cta.bulk_group [%0], [%1], %2;"
                :: "l"(gdst), "r"(ssrc), "n"(BLK * NBINS * 4) : "memory");
            asm volatile("cp.async.bulk.commit_group;" ::: "memory");
            // allow 1 in-flight group: the buffer we write next is drained
            asm volatile("cp.async.bulk.wait_group.read 1;" ::: "memory");
        }
        __syncthreads();   // gate: nobody touches the other buffer early
    }

    // keep smem alive until the last TMA read completes
    if (t == 0) {
        asm volatile("cp.async.bulk.wait_group.read 0;" ::: "memory");
    }
}

extern "C" void kernel_launch(void* const* d_in, const int* in_sizes, int n_in,
                              void* d_out, int out_size) {
    const float* expr = (const float*)d_in[0];
    const float* W1   = (const float*)d_in[1];
    const float* b1   = (const float*)d_in[2];
    const float* W2   = (const float*)d_in[3];
    const float* b2   = (const float*)d_in[4];

    float* probs = (float*)d_out;
    float* mask  = (float*)d_out + (size_t)N_ELEM * NBINS;

    setup_kernel<<<NSEG, 288>>>(W1, b1, W2, b2);
    expr_quantizer_kernel<<<PGRID, BLK>>>(expr, probs, mask);
}

// round 15
// speedup vs baseline: 1.2087x; 1.0011x over previous
#include <cuda_runtime.h>
#include <cstdint>

// Problem constants
#define B_DIM 128
#define G_DIM 20000
#define N_ELEM (B_DIM * G_DIM)   // 2,560,000
#define HID 64
#define NBM1 9                   // NUM_BINS - 1
#define NBINS 10
#define NSEG (HID + 1)           // 65 piecewise-linear segments
#define ROWF 20                  // floats per table row (A0..A8,C0..C8,pad,pad) = 80B
#define BLK 256
#define NTILE (N_ELEM / BLK)     // 10,000 tiles of 256 elements
#define PGRID 1184               // persistent CTAs: 148 SMs x 8
#define LOG2E 1.4426950408889634f

// __device__ global scratch (no allocations allowed)
__device__ float g_T[HID];                          // sorted thresholds
__device__ __align__(16) float g_tab[NSEG * ROWF];  // log2-domain (A', C') table

// ---------------------------------------------------------------------------
// Setup: build the piecewise-linear table (log2 domain), parallelized:
// grid = NSEG blocks (one segment each), 288 threads (9 warps; warp k
// reduces entry (j,k) over h with shuffles).
// logit_k(x) = b2[k] + sum_h W2[h,k] * leaky(x*w1[h] + b1[h]); the leaky
// sign pattern changes only at thr_h = -b1[h]/w1[h]. For segment j:
//   w1>0 : pre-act >= 0  <=>  rank(thr_h) < j
//   w1<0 : pre-act >= 0  <=>  rank(thr_h) >= j
//   w1==0: pre-act >= 0  <=>  b1 >= 0     (thr = +inf, excluded from search)
// ---------------------------------------------------------------------------
__global__ void setup_kernel(const float* __restrict__ W1,
                             const float* __restrict__ b1,
                             const float* __restrict__ W2,
                             const float* __restrict__ b2) {
    __shared__ float s_thr[HID];
    __shared__ int   s_rank[HID];
    __shared__ float s_w1[HID];
    __shared__ float s_b1[HID];

    int t = threadIdx.x;
    if (t < HID) {
        float w = W1[t];
        float b = b1[t];
        s_w1[t] = w;
        s_b1[t] = b;
        s_thr[t] = (w != 0.0f) ? (-b / w) : __int_as_float(0x7f800000); // +inf
    }
    __syncthreads();

    if (t < HID) {
        float thr = s_thr[t];
        int idx = 0;
        #pragma unroll
        for (int h = 0; h < HID; h++) {
            float o = s_thr[h];
            if (o < thr || (o == thr && h < t)) idx++;  // stable rank
        }
        s_rank[t] = idx;
        if (blockIdx.x == 0) g_T[idx] = thr;  // only one block writes g_T
    }
    __syncthreads();

    int j    = blockIdx.x;       // segment
    int k    = t >> 5;           // warp id = bin
    int lane = t & 31;
    if (k < NBM1) {
        float A = 0.0f, C = 0.0f;
        #pragma unroll
        for (int hh = 0; hh < 2; hh++) {
            int h = lane + 32 * hh;
            float w = s_w1[h];
            float b = s_b1[h];
            bool pos;
            if (w > 0.0f)      pos = (s_rank[h] < j);
            else if (w < 0.0f) pos = (s_rank[h] >= j);
            else               pos = (b >= 0.0f);
            float scale = pos ? 1.0f : 0.01f;
            float w2s = W2[h * NBM1 + k] * scale;
            A = fmaf(w2s, w, A);
            C = fmaf(w2s, b, C);
        }
        #pragma unroll
        for (int off = 16; off > 0; off >>= 1) {
            A += __shfl_down_sync(0xffffffffu, A, off);
            C += __shfl_down_sync(0xffffffffu, C, off);
        }
        if (lane == 0) {
            g_tab[j * ROWF + k]        = A * LOG2E;
            g_tab[j * ROWF + NBM1 + k] = (C + b2[k]) * LOG2E;
        }
    }
    if (t == 288 - 1) {  // zero row padding
        g_tab[j * ROWF + 18] = 0.0f;
        g_tab[j * ROWF + 19] = 0.0f;
    }
}

// ---------------------------------------------------------------------------
// Main: persistent CTAs, SINGLE-PHASE body, double-buffered TMA flush.
// Per tile: every thread computes its own 40B output row entirely in
// registers (predicated softmax for nonzero x, constant template for zero x)
// and writes it with 5 STS.64 — no compaction, no atomics, no scatter pass,
// only 2 barriers per tile. One cp.async.bulk per tile drains the staging
// buffer through the async proxy while the next tile is computed into the
// other buffer.
// ---------------------------------------------------------------------------
__global__ void __launch_bounds__(BLK)
expr_quantizer_kernel(const float* __restrict__ expr,
                      float* __restrict__ probs,
                      float* __restrict__ mask) {
    __shared__ __align__(16) float sOut[2][BLK * NBINS];  // 2 x 10 KB staging
    __shared__ float sT[HID];

    int t = threadIdx.x;
    if (t < HID) sT[t] = g_T[t];
    __syncthreads();

    int j = 0;  // local iteration index
    for (int tile = blockIdx.x; tile < NTILE; tile += PGRID, j++) {
        float* out = sOut[j & 1];

        int e = tile * BLK + t;
        float x = __ldg(expr + e);
        bool nz = (x != 0.0f);
        mask[e] = nz ? 1.0f : 0.0f;

        // row template: (bin0, p1..p9)
        float p0 = 1.0f;
        float p1 = 0.0f, p2 = 0.0f, p3 = 0.0f, p4 = 0.0f, p5 = 0.0f,
              p6 = 0.0f, p7 = 0.0f, p8 = 0.0f, p9 = 0.0f;

        if (nz) {
            // segment = count of sorted thresholds <= x, in [0, 64]
            int sj = 0;
            #pragma unroll
            for (int step = 64; step > 0; step >>= 1) {
                int nj = sj + step;
                if (nj <= HID && sT[nj - 1] <= x) sj = nj;
            }

            const float4* row = reinterpret_cast<const float4*>(g_tab + sj * ROWF);
            float4 r0 = __ldg(row + 0);  // A0..A3
            float4 r1 = __ldg(row + 1);  // A4..A7
            float4 r2 = __ldg(row + 2);  // A8, C0, C1, C2
            float4 r3 = __ldg(row + 3);  // C3..C6
            float4 r4 = __ldg(row + 4);  // C7, C8, pad, pad

            float l0 = fmaf(r0.x, x, r2.y);
            float l1 = fmaf(r0.y, x, r2.z);
            float l2 = fmaf(r0.z, x, r2.w);
            float l3 = fmaf(r0.w, x, r3.x);
            float l4 = fmaf(r1.x, x, r3.y);
            float l5 = fmaf(r1.y, x, r3.z);
            float l6 = fmaf(r1.z, x, r3.w);
            float l7 = fmaf(r1.w, x, r4.x);
            float l8 = fmaf(r2.x, x, r4.y);

            float m0 = fmaxf(l0, l1), m1 = fmaxf(l2, l3);
            float m2 = fmaxf(l4, l5), m3 = fmaxf(l6, l7);
            float mx = fmaxf(fmaxf(fmaxf(m0, m1), fmaxf(m2, m3)), l8);

            float e0 = exp2f(l0 - mx), e1 = exp2f(l1 - mx), e2 = exp2f(l2 - mx);
            float e3 = exp2f(l3 - mx), e4 = exp2f(l4 - mx), e5 = exp2f(l5 - mx);
            float e6 = exp2f(l6 - mx), e7 = exp2f(l7 - mx), e8 = exp2f(l8 - mx);

            float s0 = e0 + e1, s1 = e2 + e3, s2 = e4 + e5, s3 = e6 + e7;
            float sum = ((s0 + s1) + (s2 + s3)) + e8;
            float inv = __fdividef(1.0f, sum);

            p0 = 0.0f;
            p1 = e0 * inv; p2 = e1 * inv; p3 = e2 * inv;
            p4 = e3 * inv; p5 = e4 * inv; p6 = e5 * inv;
            p7 = e6 * inv; p8 = e7 * inv; p9 = e8 * inv;
        }

        // write own 40B row: 5 x STS.64 (base = t*40B, 8B-aligned)
        {
            float2* row2 = reinterpret_cast<float2*>(out + t * NBINS);
            row2[0] = make_float2(p0, p1);
            row2[1] = make_float2(p2, p3);
            row2[2] = make_float2(p4, p5);
            row2[3] = make_float2(p6, p7);
            row2[4] = make_float2(p8, p9);
        }
        __syncthreads();

        // flush (pipelined): TMA reads smem via async proxy, writes L2
        if (t == 0) {
            asm volatile("fence.proxy.async.shared::cta;" ::: "memory");
            uint32_t ssrc = (uint32_t)__cvta_generic_to_shared(out);
            void* gdst = (void*)(probs + (size_t)tile * (BLK * NBINS));
            asm volatile(
                "cp.async.bulk.global.shared::cta.bulk_group [%0], [%1], %2;"
                :: "l"(gdst), "r"(ssrc), "n"(BLK * NBINS * 4) : "memory");
            asm volatile("cp.async.bulk.commit_group;" ::: "memory");
            // allow 1 in-flight group: the buffer we write next is drained
            asm volatile("cp.async.bulk.wait_group.read 1;" ::: "memory");
        }
        __syncthreads();   // gate: nobody refills the other buffer early
    }

    // keep smem alive until the last TMA read completes
    if (t == 0) {
        asm volatile("cp.async.bulk.wait_group.read 0;" ::: "memory");
    }
}

extern "C" void kernel_launch(void* const* d_in, const int* in_sizes, int n_in,
                              void* d_out, int out_size) {
    const float* expr = (const float*)d_in[0];
    const float* W1   = (const float*)d_in[1];
    const float* b1   = (const float*)d_in[2];
    const float* W2   = (const float*)d_in[3];
    const float* b2   = (const float*)d_in[4];

    float* probs = (float*)d_out;
    float* mask  = (float*)d_out + (size_t)N_ELEM * NBINS;

    setup_kernel<<<NSEG, 288>>>(W1, b1, W2, b2);
    expr_quantizer_kernel<<<PGRID, BLK>>>(expr, probs, mask);
}